// round 6
// baseline (speedup 1.0000x reference)
#include <cuda_runtime.h>
#include <cuda_bf16.h>
#include <math.h>
#include <stdint.h>

#define DDIM 256
#define NQMAX 40000

// ---------------- scratch (device globals; zero-initialized) -----------------
__device__ __align__(16) float g_v  [NQMAX * DDIM];   // value projection (fp32, sampled)
__device__ __align__(16) float g_oa [NQMAX * 144];    // offsets+logits
__device__ __align__(16) float g_tmp[NQMAX * DDIM];   // out-proj / W2 result
__device__ __align__(16) float g_y  [NQMAX * DDIM];   // ln1 out (fp32 residual)

// bf16 hi/lo activation buffers
__device__ __align__(16) __nv_bfloat16 g_qh[NQMAX * DDIM], g_ql[NQMAX * DDIM];
__device__ __align__(16) __nv_bfloat16 g_ah[NQMAX * DDIM], g_al[NQMAX * DDIM];
__device__ __align__(16) __nv_bfloat16 g_mh[NQMAX * DDIM], g_ml[NQMAX * DDIM];
__device__ __align__(16) __nv_bfloat16 g_yh[NQMAX * DDIM], g_yl[NQMAX * DDIM];
__device__ __align__(16) __nv_bfloat16 g_hh[NQMAX * DDIM], g_hl[NQMAX * DDIM];

// transposed + bf16-split weights: [N][K=256] (boa padded to 256 rows, zeros)
__device__ __align__(16) __nv_bfloat16 g_bv_h[DDIM * DDIM], g_bv_l[DDIM * DDIM];
__device__ __align__(16) __nv_bfloat16 g_bo_h[DDIM * DDIM], g_bo_l[DDIM * DDIM];
__device__ __align__(16) __nv_bfloat16 g_b1_h[DDIM * DDIM], g_b1_l[DDIM * DDIM];
__device__ __align__(16) __nv_bfloat16 g_b2_h[DDIM * DDIM], g_b2_l[DDIM * DDIM];
__device__ __align__(16) __nv_bfloat16 g_boa_h[DDIM * DDIM], g_boa_l[DDIM * DDIM];
__device__ __align__(16) float g_boa[144];

// ---------------- helpers ------------------------------------------------------
__device__ __forceinline__ uint32_t smem_u32(const void* p) {
    uint32_t a;
    asm("{ .reg .u64 t; cvta.to.shared.u64 t, %1; cvt.u32.u64 %0, t; }" : "=r"(a) : "l"(p));
    return a;
}
__device__ __forceinline__ uint32_t pack_bf16(__nv_bfloat16 x, __nv_bfloat16 y) {
    __nv_bfloat162 t(x, y);
    return *reinterpret_cast<uint32_t*>(&t);
}
__device__ __forceinline__ float gelu_exact(float x) {
    return 0.5f * x * (1.0f + erff(x * 0.70710678118654752f));
}

#define LDSM4(r, addr) \
    asm volatile("ldmatrix.sync.aligned.m8n8.x4.shared.b16 {%0,%1,%2,%3}, [%4];" \
        : "=r"((r)[0]), "=r"((r)[1]), "=r"((r)[2]), "=r"((r)[3]) : "r"(addr))

#define CP_ASYNC16Z(dst, src, sz) \
    asm volatile("cp.async.ca.shared.global [%0], [%1], 16, %2;" \
                 :: "r"(dst), "l"(src), "r"(sz))
#define CP_COMMIT() asm volatile("cp.async.commit_group;" ::: "memory")
#define CP_WAIT(n)  asm volatile("cp.async.wait_group %0;" :: "n"(n) : "memory")

__device__ __forceinline__ void mma_bf16(float* d, const uint32_t* a,
                                         uint32_t b0, uint32_t b1) {
    asm volatile(
        "mma.sync.aligned.m16n8k16.row.col.f32.bf16.bf16.f32 "
        "{%0,%1,%2,%3}, {%4,%5,%6,%7}, {%8,%9}, {%0,%1,%2,%3};"
        : "+f"(d[0]), "+f"(d[1]), "+f"(d[2]), "+f"(d[3])
        : "r"(a[0]), "r"(a[1]), "r"(a[2]), "r"(a[3]), "r"(b0), "r"(b1));
}

// ---------------- HMMA GEMM v4: 4-stage, single-sync cp.async pipeline ---------
// C = A[M][256] @ B^T + bias.  CTA tile 128x128, 8 warps (4x2), BK=16.
// MODE 0: write fp32 Cf.  MODE 1: gelu, write bf16 Ch/Cl only.
// FULLN=1: all 128 cols valid; FULLN=0: clamp warp nb-range by N (oa GEMM).
template<int MODE, int FULLN>
__global__ __launch_bounds__(256, 2)
void gemm_cp(const __nv_bfloat16* __restrict__ Ah, const __nv_bfloat16* __restrict__ Al,
             const __nv_bfloat16* __restrict__ Bh, const __nv_bfloat16* __restrict__ Bl,
             const float* __restrict__ bias,
             float* __restrict__ Cf,
             __nv_bfloat16* __restrict__ Ch, __nv_bfloat16* __restrict__ Cl,
             int M, int N) {
    extern __shared__ __align__(128) char smem[];
    const uint32_t sb = smem_u32(smem);
    const int tid = threadIdx.x;
    const int wid = tid >> 5;
    const int lane = tid & 31;
    const int m0 = blockIdx.y * 128;
    const int n0 = blockIdx.x * 128;
    const int wr = wid & 3;
    const int wc = wid >> 2;

    constexpr int RB = 48;            // smem row bytes (32 data + 16 pad)
    constexpr int STG = 128 * RB;     // 6144 per array
    constexpr int SSTR = 4 * STG;     // 24576 per stage (4 stages = 96KB)

    // warp nb range (16-col groups within this warp's 64-col slab)
    int nbLim;
    if (FULLN) nbLim = 4;
    else {
        const int rem = N - n0 - wc * 64;
        nbLim = rem >= 64 ? 4 : (rem <= 0 ? 0 : (rem + 15) >> 4);
    }

    const int row = tid >> 1;
    const int half = tid & 1;
    const uint32_t dstOff = row * RB + half * 16;
    const uint32_t aValid = (m0 + row < M) ? 16u : 0u;
    const __nv_bfloat16* aSrcH = Ah + (size_t)(m0 + row) * DDIM + half * 8;
    const __nv_bfloat16* aSrcL = Al + (size_t)(m0 + row) * DDIM + half * 8;
    const __nv_bfloat16* bSrcH = Bh + (size_t)(n0 + row) * DDIM + half * 8;
    const __nv_bfloat16* bSrcL = Bl + (size_t)(n0 + row) * DDIM + half * 8;

#define ISSUE(c) do { \
    const uint32_t base = sb + ((c) & 3) * SSTR + dstOff; \
    CP_ASYNC16Z(base,           aSrcH + (c) * 16, aValid); \
    CP_ASYNC16Z(base + STG,     aSrcL + (c) * 16, aValid); \
    CP_ASYNC16Z(base + 2 * STG, bSrcH + (c) * 16, 16u); \
    CP_ASYNC16Z(base + 3 * STG, bSrcL + (c) * 16, 16u); \
    CP_COMMIT(); } while (0)

    float acc[2][8][4];
#pragma unroll
    for (int i = 0; i < 2; ++i)
#pragma unroll
        for (int j = 0; j < 8; ++j)
#pragma unroll
            for (int k = 0; k < 4; ++k) acc[i][j][k] = 0.f;

    ISSUE(0);
    ISSUE(1);
    ISSUE(2);

    const uint32_t lmA = (wr * 32 + (lane & 15)) * RB + (lane >> 4) * 16;
    const uint32_t lmB = (wc * 64 + (lane & 15)) * RB + (lane >> 4) * 16;

    for (int c = 0; c < 16; ++c) {
        const uint32_t stg = sb + (c & 3) * SSTR;
        // tail-correct waits: guarantee chunk c's group retired
        if (c <= 13)      CP_WAIT(2);
        else if (c == 14) CP_WAIT(1);
        else              CP_WAIT(0);
        __syncthreads();
        // stage (c+3)&3 == (c-1)&3 was fully consumed before this sync
        if (c + 3 < 16) ISSUE(c + 3);

        uint32_t ah[2][4], al[2][4];
#pragma unroll
        for (int mr = 0; mr < 2; ++mr) {
            LDSM4(ah[mr], stg + lmA + mr * 16 * RB);
            LDSM4(al[mr], stg + STG + lmA + mr * 16 * RB);
        }

        uint32_t bh[2][4], bl[2][4];
        if (nbLim > 0) {
            LDSM4(bh[0], stg + 2 * STG + lmB);
            LDSM4(bl[0], stg + 3 * STG + lmB);
        }
#pragma unroll 4
        for (int nb = 0; nb < nbLim; ++nb) {
            const int cur = nb & 1;
            if (nb + 1 < nbLim) {
                LDSM4(bh[cur ^ 1], stg + 2 * STG + lmB + (nb + 1) * 16 * RB);
                LDSM4(bl[cur ^ 1], stg + 3 * STG + lmB + (nb + 1) * 16 * RB);
            }
#pragma unroll
            for (int mr = 0; mr < 2; ++mr) {
                mma_bf16(acc[mr][nb * 2 + 0], ah[mr], bh[cur][0], bh[cur][2]);
                mma_bf16(acc[mr][nb * 2 + 1], ah[mr], bh[cur][1], bh[cur][3]);
                mma_bf16(acc[mr][nb * 2 + 0], ah[mr], bl[cur][0], bl[cur][2]);
                mma_bf16(acc[mr][nb * 2 + 1], ah[mr], bl[cur][1], bl[cur][3]);
                mma_bf16(acc[mr][nb * 2 + 0], al[mr], bh[cur][0], bh[cur][2]);
                mma_bf16(acc[mr][nb * 2 + 1], al[mr], bh[cur][1], bh[cur][3]);
            }
        }
    }

    // ---- epilogue ----
#pragma unroll
    for (int mr = 0; mr < 2; ++mr) {
        const int r0 = m0 + wr * 32 + mr * 16 + (lane >> 2);
#pragma unroll
        for (int f = 0; f < 8; ++f) {
            const int col = n0 + wc * 64 + f * 8 + (lane & 3) * 2;
            if (col >= N) continue;
            const float b0 = bias[col], b1 = bias[col + 1];
#pragma unroll
            for (int h = 0; h < 2; ++h) {
                const int r = r0 + h * 8;
                if (r >= M) continue;
                float x0 = acc[mr][f][h * 2 + 0] + b0;
                float x1 = acc[mr][f][h * 2 + 1] + b1;
                if (MODE == 1) {
                    x0 = gelu_exact(x0); x1 = gelu_exact(x1);
                    const __nv_bfloat16 h0 = __float2bfloat16(x0);
                    const __nv_bfloat16 h1 = __float2bfloat16(x1);
                    const uint32_t hv = pack_bf16(h0, h1);
                    const uint32_t lv = pack_bf16(
                        __float2bfloat16(x0 - __bfloat162float(h0)),
                        __float2bfloat16(x1 - __bfloat162float(h1)));
                    *reinterpret_cast<uint32_t*>(Ch + (size_t)r * DDIM + col) = hv;
                    *reinterpret_cast<uint32_t*>(Cl + (size_t)r * DDIM + col) = lv;
                } else {
                    *reinterpret_cast<float2*>(Cf + (size_t)r * N + col) = make_float2(x0, x1);
                }
            }
        }
    }
#undef ISSUE
}

// ---------------- split fp32 activations -> bf16 hi/lo -------------------------
__global__ __launch_bounds__(256)
void split_act(const float* __restrict__ x, __nv_bfloat16* __restrict__ h,
               __nv_bfloat16* __restrict__ l, int n4) {
    const int i = blockIdx.x * 256 + threadIdx.x;
    if (i >= n4) return;
    const float4 v = __ldg(reinterpret_cast<const float4*>(x) + i);
    const __nv_bfloat16 h0 = __float2bfloat16(v.x);
    const __nv_bfloat16 h1 = __float2bfloat16(v.y);
    const __nv_bfloat16 h2 = __float2bfloat16(v.z);
    const __nv_bfloat16 h3 = __float2bfloat16(v.w);
    uint2 hv = make_uint2(pack_bf16(h0, h1), pack_bf16(h2, h3));
    uint2 lv = make_uint2(
        pack_bf16(__float2bfloat16(v.x - __bfloat162float(h0)),
                  __float2bfloat16(v.y - __bfloat162float(h1))),
        pack_bf16(__float2bfloat16(v.z - __bfloat162float(h2)),
                  __float2bfloat16(v.w - __bfloat162float(h3))));
    *reinterpret_cast<uint2*>(h + (size_t)i * 4) = hv;
    *reinterpret_cast<uint2*>(l + (size_t)i * 4) = lv;
}

// ---------------- weight transpose + bf16 split --------------------------------
__global__ __launch_bounds__(256)
void convert_weights(const float* __restrict__ Wv, const float* __restrict__ Wo,
                     const float* __restrict__ W1, const float* __restrict__ W2,
                     const float* __restrict__ Woff, const float* __restrict__ Wattn,
                     const float* __restrict__ boff, const float* __restrict__ battn) {
    const int b = blockIdx.x;
    const int k = threadIdx.x;
    if (b == 1168) {
        if (k < 96) g_boa[k] = boff[k];
        else if (k < 144) g_boa[k] = battn[k - 96];
        return;
    }
    const float* W; __nv_bfloat16* oh; __nv_bfloat16* ol; int n, nout, N;
    if (b < 256)       { W = Wv; oh = g_bv_h; ol = g_bv_l; n = b;        nout = n; N = 256; }
    else if (b < 512)  { W = Wo; oh = g_bo_h; ol = g_bo_l; n = b - 256;  nout = n; N = 256; }
    else if (b < 768)  { W = W1; oh = g_b1_h; ol = g_b1_l; n = b - 512;  nout = n; N = 256; }
    else if (b < 1024) { W = W2; oh = g_b2_h; ol = g_b2_l; n = b - 768;  nout = n; N = 256; }
    else {
        nout = b - 1024;
        oh = g_boa_h; ol = g_boa_l;
        if (nout < 96) { W = Woff;  n = nout;      N = 96; }
        else           { W = Wattn; n = nout - 96; N = 48; }
    }
    const float x = W[(size_t)k * N + n];
    const __nv_bfloat16 h = __float2bfloat16(x);
    const __nv_bfloat16 l = __float2bfloat16(x - __bfloat162float(h));
    oh[(size_t)nout * DDIM + k] = h;
    ol[(size_t)nout * DDIM + k] = l;
}

// ---------------- MSDA sampling: corner-parallel, writes bf16 hi/lo ------------
__global__ __launch_bounds__(256)
void msda_sample_kernel(const float* __restrict__ oa, const float* __restrict__ v,
                        const float* __restrict__ ref, const int* __restrict__ ss,
                        __nv_bfloat16* __restrict__ oh, __nv_bfloat16* __restrict__ ol) {
    const int q = blockIdx.x;
    const int h = threadIdx.x >> 5;
    const int lane = threadIdx.x & 31;
    const int corner = lane >> 3;
    const int dx = corner & 1;
    const int dy = corner >> 1;
    const int cg = lane & 7;

    const int H = ss[0];
    const int W = ss[1];

    const float bx = __ldg(ref + q * 2 + 0) * (float)W - 0.5f;
    const float by = __ldg(ref + q * 2 + 1) * (float)H - 0.5f;

    const float* qa = oa + (size_t)q * 144;
    float lg[6];
    float mx = -1e30f;
#pragma unroll
    for (int p = 0; p < 6; ++p) {
        lg[p] = __ldg(qa + 96 + h * 6 + p);
        mx = fmaxf(mx, lg[p]);
    }
    float s = 0.f;
#pragma unroll
    for (int p = 0; p < 6; ++p) { lg[p] = __expf(lg[p] - mx); s += lg[p]; }
    const float inv = 1.f / s;

    const float4* vh = reinterpret_cast<const float4*>(v) + h * 8 + cg;
    float4 acc = make_float4(0.f, 0.f, 0.f, 0.f);

#pragma unroll
    for (int p = 0; p < 6; ++p) {
        const float ox = __ldg(qa + h * 12 + p * 2 + 0);
        const float oy = __ldg(qa + h * 12 + p * 2 + 1);
        const float lx = bx + ox;
        const float ly = by + oy;
        const float x0f = floorf(lx);
        const float y0f = floorf(ly);
        const float fx = lx - x0f;
        const float fy = ly - y0f;
        const int xi = (int)x0f + dx;
        const int yi = (int)y0f + dy;
        const float wx = dx ? fx : 1.f - fx;
        const float wy = dy ? fy : 1.f - fy;
        const bool valid = (xi >= 0) & (xi < W) & (yi >= 0) & (yi < H);
        const float w = valid ? (lg[p] * inv) * wx * wy : 0.f;
        const int xc = min(max(xi, 0), W - 1);
        const int yc = min(max(yi, 0), H - 1);
        const float4 val = __ldg(vh + (size_t)(yc * W + xc) * 64);
        acc.x += w * val.x;
        acc.y += w * val.y;
        acc.z += w * val.z;
        acc.w += w * val.w;
    }

#pragma unroll
    for (int o = 8; o <= 16; o <<= 1) {
        acc.x += __shfl_xor_sync(0xffffffffu, acc.x, o);
        acc.y += __shfl_xor_sync(0xffffffffu, acc.y, o);
        acc.z += __shfl_xor_sync(0xffffffffu, acc.z, o);
        acc.w += __shfl_xor_sync(0xffffffffu, acc.w, o);
    }
    if (lane < 8) {
        const __nv_bfloat16 h0 = __float2bfloat16(acc.x);
        const __nv_bfloat16 h1 = __float2bfloat16(acc.y);
        const __nv_bfloat16 h2 = __float2bfloat16(acc.z);
        const __nv_bfloat16 h3 = __float2bfloat16(acc.w);
        uint2 hv = make_uint2(pack_bf16(h0, h1), pack_bf16(h2, h3));
        uint2 lv = make_uint2(
            pack_bf16(__float2bfloat16(acc.x - __bfloat162float(h0)),
                      __float2bfloat16(acc.y - __bfloat162float(h1))),
            pack_bf16(__float2bfloat16(acc.z - __bfloat162float(h2)),
                      __float2bfloat16(acc.w - __bfloat162float(h3))));
        const size_t o0 = (size_t)q * DDIM + h * 32 + cg * 4;
        *reinterpret_cast<uint2*>(oh + o0) = hv;
        *reinterpret_cast<uint2*>(ol + o0) = lv;
    }
}

// ---------------- fused residual + LayerNorm -----------------------------------
template<int SPLIT>
__global__ __launch_bounds__(256)
void ln_kernel(const float* __restrict__ x, const float* __restrict__ res,
               const float* __restrict__ g, const float* __restrict__ b,
               float* __restrict__ out,
               __nv_bfloat16* __restrict__ oh, __nv_bfloat16* __restrict__ ol) {
    const int row = blockIdx.x;
    const int tid = threadIdx.x;
    const float v = x[(size_t)row * DDIM + tid] + res[(size_t)row * DDIM + tid];

    float s = v, s2 = v * v;
#pragma unroll
    for (int o = 16; o; o >>= 1) {
        s  += __shfl_xor_sync(0xffffffffu, s, o);
        s2 += __shfl_xor_sync(0xffffffffu, s2, o);
    }
    __shared__ float sh[16];
    const int w = tid >> 5, lane = tid & 31;
    if (lane == 0) { sh[w] = s; sh[w + 8] = s2; }
    __syncthreads();
    if (tid == 0) {
        float a = 0.f, c = 0.f;
#pragma unroll
        for (int i = 0; i < 8; ++i) { a += sh[i]; c += sh[i + 8]; }
        sh[0] = a; sh[8] = c;
    }
    __syncthreads();
    const float mean = sh[0] * (1.f / 256.f);
    const float var  = sh[8] * (1.f / 256.f) - mean * mean;
    const float rstd = rsqrtf(var + 1e-5f);
    const float o = (v - mean) * rstd * g[tid] + b[tid];
    out[(size_t)row * DDIM + tid] = o;
    if (SPLIT) {
        const __nv_bfloat16 hh = __float2bfloat16(o);
        oh[(size_t)row * DDIM + tid] = hh;
        ol[(size_t)row * DDIM + tid] = __float2bfloat16(o - __bfloat162float(hh));
    }
}

// ---------------- launch --------------------------------------------------------
extern "C" void kernel_launch(void* const* d_in, const int* in_sizes, int n_in,
                              void* d_out, int out_size) {
    const float* query  = (const float*)d_in[0];
    const float* value  = (const float*)d_in[1];
    const float* refp   = (const float*)d_in[2];
    const int*   ss     = (const int*)d_in[3];
    const float* W_off  = (const float*)d_in[5];
    const float* b_off  = (const float*)d_in[6];
    const float* W_attn = (const float*)d_in[7];
    const float* b_attn = (const float*)d_in[8];
    const float* W_val  = (const float*)d_in[9];
    const float* b_val  = (const float*)d_in[10];
    const float* W_out  = (const float*)d_in[11];
    const float* b_out  = (const float*)d_in[12];
    const float* ln1_g  = (const float*)d_in[13];
    const float* ln1_b  = (const float*)d_in[14];
    const float* W1     = (const float*)d_in[15];
    const float* b1     = (const float*)d_in[16];
    const float* W2     = (const float*)d_in[17];
    const float* b2     = (const float*)d_in[18];
    const float* ln2_g  = (const float*)d_in[19];
    const float* ln2_b  = (const float*)d_in[20];
    float* out = (float*)d_out;

    const int M  = in_sizes[0] / DDIM;
    const int Mv = in_sizes[1] / DDIM;

    float *pv, *poa, *ptmp, *py, *pboa;
    __nv_bfloat16 *qh, *ql, *avh, *avl, *mh, *ml, *yh, *yl, *hh, *hl;
    __nv_bfloat16 *bvh, *bvl, *boh, *bol, *b1h, *b1l, *b2h, *b2l, *boah, *boal;
    cudaGetSymbolAddress((void**)&pv,   g_v);
    cudaGetSymbolAddress((void**)&poa,  g_oa);
    cudaGetSymbolAddress((void**)&ptmp, g_tmp);
    cudaGetSymbolAddress((void**)&py,   g_y);
    cudaGetSymbolAddress((void**)&pboa, g_boa);
    cudaGetSymbolAddress((void**)&qh,   g_qh);  cudaGetSymbolAddress((void**)&ql, g_ql);
    cudaGetSymbolAddress((void**)&avh,  g_ah);  cudaGetSymbolAddress((void**)&avl, g_al);
    cudaGetSymbolAddress((void**)&mh,   g_mh);  cudaGetSymbolAddress((void**)&ml, g_ml);
    cudaGetSymbolAddress((void**)&yh,   g_yh);  cudaGetSymbolAddress((void**)&yl, g_yl);
    cudaGetSymbolAddress((void**)&hh,   g_hh);  cudaGetSymbolAddress((void**)&hl, g_hl);
    cudaGetSymbolAddress((void**)&bvh,  g_bv_h); cudaGetSymbolAddress((void**)&bvl, g_bv_l);
    cudaGetSymbolAddress((void**)&boh,  g_bo_h); cudaGetSymbolAddress((void**)&bol, g_bo_l);
    cudaGetSymbolAddress((void**)&b1h,  g_b1_h); cudaGetSymbolAddress((void**)&b1l, g_b1_l);
    cudaGetSymbolAddress((void**)&b2h,  g_b2_h); cudaGetSymbolAddress((void**)&b2l, g_b2_l);
    cudaGetSymbolAddress((void**)&boah, g_boa_h); cudaGetSymbolAddress((void**)&boal, g_boa_l);

    const int SMEM = 4 * 4 * 128 * 48;  // 98304 bytes (4 stages x 24KB)
    cudaFuncSetAttribute((gemm_cp<0, 1>), cudaFuncAttributeMaxDynamicSharedMemorySize, SMEM);
    cudaFuncSetAttribute((gemm_cp<1, 1>), cudaFuncAttributeMaxDynamicSharedMemorySize, SMEM);
    cudaFuncSetAttribute((gemm_cp<0, 0>), cudaFuncAttributeMaxDynamicSharedMemorySize, SMEM);

    const int gM  = (M + 127) / 128;
    const int gMv = (Mv + 127) / 128;

    // 0) weight + activation conversion
    convert_weights<<<1169, 256>>>(W_val, W_out, W1, W2, W_off, W_attn, b_off, b_attn);
    split_act<<<(M * 64 + 255) / 256, 256>>>(query, qh, ql, M * 64);
    split_act<<<(Mv * 64 + 255) / 256, 256>>>(value, avh, avl, Mv * 64);
    // 1) value projection
    gemm_cp<0, 1><<<dim3(2, gMv), 256, SMEM>>>(avh, avl, bvh, bvl, b_val, pv, nullptr, nullptr, Mv, DDIM);
    // 2) fused offsets+attn logits GEMM (N=144, nb-clamped)
    gemm_cp<0, 0><<<dim3(2, gM), 256, SMEM>>>(qh, ql, boah, boal, pboa, poa, nullptr, nullptr, M, 144);
    // 3) deformable sampling -> bf16 hi/lo
    msda_sample_kernel<<<M, 256>>>(poa, pv, refp, ss, mh, ml);
    // 4) output projection + residual + LN1
    gemm_cp<0, 1><<<dim3(2, gM), 256, SMEM>>>(mh, ml, boh, bol, b_out, ptmp, nullptr, nullptr, M, DDIM);
    ln_kernel<1><<<M, 256>>>(ptmp, query, ln1_g, ln1_b, py, yh, yl);
    // 5) FFN
    gemm_cp<1, 1><<<dim3(2, gM), 256, SMEM>>>(yh, yl, b1h, b1l, b1, nullptr, hh, hl, M, DDIM);
    gemm_cp<0, 1><<<dim3(2, gM), 256, SMEM>>>(hh, hl, b2h, b2l, b2, ptmp, nullptr, nullptr, M, DDIM);
    ln_kernel<0><<<M, 256>>>(ptmp, py, ln2_g, ln2_b, out, nullptr, nullptr);
}

// round 7
// speedup vs baseline: 1.2128x; 1.2128x over previous
#include <cuda_runtime.h>
#include <cuda_bf16.h>
#include <math.h>
#include <stdint.h>

#define DDIM 256
#define NQMAX 40000

// ---------------- scratch (device globals; zero-initialized, no allocation) --
__device__ __align__(16) float g_v   [NQMAX * DDIM];
__device__ __align__(16) float g_oa  [NQMAX * 144];
__device__ __align__(16) float g_msda[NQMAX * DDIM];
__device__ __align__(16) float g_tmp [NQMAX * DDIM];
__device__ __align__(16) float g_y   [NQMAX * DDIM];

// transposed + bf16-split weights: [N][K=256]   (oa padded to 256 rows, zeros)
__device__ __align__(16) __nv_bfloat16 g_bv_h[DDIM * DDIM];
__device__ __align__(16) __nv_bfloat16 g_bv_l[DDIM * DDIM];
__device__ __align__(16) __nv_bfloat16 g_bo_h[DDIM * DDIM];
__device__ __align__(16) __nv_bfloat16 g_bo_l[DDIM * DDIM];
__device__ __align__(16) __nv_bfloat16 g_b1_h[DDIM * DDIM];
__device__ __align__(16) __nv_bfloat16 g_b1_l[DDIM * DDIM];
__device__ __align__(16) __nv_bfloat16 g_b2_h[DDIM * DDIM];
__device__ __align__(16) __nv_bfloat16 g_b2_l[DDIM * DDIM];
__device__ __align__(16) __nv_bfloat16 g_boa_h[DDIM * DDIM];
__device__ __align__(16) __nv_bfloat16 g_boa_l[DDIM * DDIM];
__device__ __align__(16) float g_boa[144];

// ---------------- helpers ------------------------------------------------------
__device__ __forceinline__ uint32_t smem_u32(const void* p) {
    uint32_t a;
    asm("{ .reg .u64 t; cvta.to.shared.u64 t, %1; cvt.u32.u64 %0, t; }" : "=r"(a) : "l"(p));
    return a;
}

__device__ __forceinline__ uint32_t pack_bf16(__nv_bfloat16 x, __nv_bfloat16 y) {
    __nv_bfloat162 t(x, y);
    return *reinterpret_cast<uint32_t*>(&t);
}

__device__ __forceinline__ float gelu_exact(float x) {
    return 0.5f * x * (1.0f + erff(x * 0.70710678118654752f));
}

#define LDSM4(r, addr) \
    asm volatile("ldmatrix.sync.aligned.m8n8.x4.shared.b16 {%0,%1,%2,%3}, [%4];" \
        : "=r"((r)[0]), "=r"((r)[1]), "=r"((r)[2]), "=r"((r)[3]) : "r"(addr))

#define CP_ASYNC16(dst, src) \
    asm volatile("cp.async.ca.shared.global [%0], [%1], 16;" :: "r"(dst), "l"(src))
#define CP_COMMIT() asm volatile("cp.async.commit_group;" ::: "memory")
#define CP_WAIT(n)  asm volatile("cp.async.wait_group %0;" :: "n"(n) : "memory")

__device__ __forceinline__ void mma_bf16(float* d, const uint32_t* a,
                                         uint32_t b0, uint32_t b1) {
    asm volatile(
        "mma.sync.aligned.m16n8k16.row.col.f32.bf16.bf16.f32 "
        "{%0,%1,%2,%3}, {%4,%5,%6,%7}, {%8,%9}, {%0,%1,%2,%3};"
        : "+f"(d[0]), "+f"(d[1]), "+f"(d[2]), "+f"(d[3])
        : "r"(a[0]), "r"(a[1]), "r"(a[2]), "r"(a[3]), "r"(b0), "r"(b1));
}

// ---------------- HMMA GEMM (R4 baseline + nb clamp for narrow N) --------------
// C = A[M][256] @ B^T + bias.  CTA tile 128x128, 8 warps (4x2), BK=16.
// MODE 0: +bias; MODE 1: +bias then exact GELU.
// FULLN=1: all warp columns valid. FULLN=0: clamp warp's nb range by N.
template<int MODE, int FULLN>
__global__ __launch_bounds__(256, 2)
void gemm_mma(const float* __restrict__ A,
              const __nv_bfloat16* __restrict__ Bh,
              const __nv_bfloat16* __restrict__ Bl,
              const float* __restrict__ bias,
              float* __restrict__ C, int M, int N) {
    extern __shared__ __align__(128) char smem[];
    const uint32_t sb = smem_u32(smem);
    const int tid = threadIdx.x;
    const int wid = tid >> 5;
    const int lane = tid & 31;
    const int m0 = blockIdx.y * 128;
    const int n0 = blockIdx.x * 128;
    const int wr = wid & 3;
    const int wc = wid >> 2;

    constexpr int RB = 48;         // smem row bytes (32 data + 16 pad)
    constexpr int STG = 128 * RB;  // 6144 bytes per buffer
    const uint32_t offAh = 0, offAl = 2 * STG, offBh = 4 * STG, offBl = 6 * STG;

    // valid nb range for this warp (16-col groups inside its 64-col slab)
    int nbLim;
    if (FULLN) nbLim = 4;
    else {
        const int rem = N - n0 - wc * 64;
        nbLim = rem >= 64 ? 4 : (rem <= 0 ? 0 : (rem + 15) >> 4);
    }

    float acc[2][8][4];
#pragma unroll
    for (int i = 0; i < 2; ++i)
#pragma unroll
        for (int j = 0; j < 8; ++j)
#pragma unroll
            for (int k = 0; k < 4; ++k) acc[i][j][k] = 0.f;

    float4 pa[2];
    const int brow = tid >> 1;
    const int bcol = (tid & 1) * 16;
    const __nv_bfloat16* bSrcH = Bh + (size_t)(n0 + brow) * DDIM + (tid & 1) * 8;
    const __nv_bfloat16* bSrcL = Bl + (size_t)(n0 + brow) * DDIM + (tid & 1) * 8;
    const uint32_t bDstOff = brow * RB + bcol;

#define ISSUE_B(c, s) do { \
    CP_ASYNC16(sb + offBh + (s) * STG + bDstOff, bSrcH + (c) * 16); \
    CP_ASYNC16(sb + offBl + (s) * STG + bDstOff, bSrcL + (c) * 16); \
    CP_COMMIT(); } while (0)

#define LOAD_A(c) do { \
    _Pragma("unroll") \
    for (int i = 0; i < 2; ++i) { \
        const int slot = tid + i * 256; \
        const int r = slot >> 2, qq = slot & 3; \
        if (m0 + r < M) \
            pa[i] = *reinterpret_cast<const float4*>(A + (size_t)(m0 + r) * DDIM + (c) * 16 + qq * 4); \
        else pa[i] = make_float4(0.f, 0.f, 0.f, 0.f); \
    } } while (0)

#define STORE_A(s) do { \
    _Pragma("unroll") \
    for (int i = 0; i < 2; ++i) { \
        const int slot = tid + i * 256; \
        const int r = slot >> 2, qq = slot & 3; \
        __nv_bfloat16 h0 = __float2bfloat16(pa[i].x); \
        __nv_bfloat16 h1 = __float2bfloat16(pa[i].y); \
        __nv_bfloat16 h2 = __float2bfloat16(pa[i].z); \
        __nv_bfloat16 h3 = __float2bfloat16(pa[i].w); \
        uint2 hv = make_uint2(pack_bf16(h0, h1), pack_bf16(h2, h3)); \
        uint2 lv = make_uint2( \
            pack_bf16(__float2bfloat16(pa[i].x - __bfloat162float(h0)), \
                      __float2bfloat16(pa[i].y - __bfloat162float(h1))), \
            pack_bf16(__float2bfloat16(pa[i].z - __bfloat162float(h2)), \
                      __float2bfloat16(pa[i].w - __bfloat162float(h3)))); \
        *reinterpret_cast<uint2*>(smem + offAh + (s) * STG + r * RB + qq * 8) = hv; \
        *reinterpret_cast<uint2*>(smem + offAl + (s) * STG + r * RB + qq * 8) = lv; \
    } } while (0)

    ISSUE_B(0, 0);
    LOAD_A(0);

    const uint32_t lmA = (wr * 32 + (lane & 15)) * RB + (lane >> 4) * 16;
    const uint32_t lmB = (wc * 64 + (lane & 15)) * RB + (lane >> 4) * 16;

    for (int c = 0; c < 16; ++c) {
        const int s = c & 1;
        STORE_A(s);
        if (c < 15) { ISSUE_B(c + 1, s ^ 1); CP_WAIT(1); }
        else        { CP_WAIT(0); }
        __syncthreads();
        if (c < 15) LOAD_A(c + 1);

        uint32_t ah[2][4], al[2][4];
#pragma unroll
        for (int mr = 0; mr < 2; ++mr) {
            LDSM4(ah[mr], sb + offAh + s * STG + lmA + mr * 16 * RB);
            LDSM4(al[mr], sb + offAl + s * STG + lmA + mr * 16 * RB);
        }
#pragma unroll 4
        for (int nb = 0; nb < (FULLN ? 4 : nbLim); ++nb) {
            uint32_t bh[4], bl[4];
            LDSM4(bh, sb + offBh + s * STG + lmB + nb * 16 * RB);
            LDSM4(bl, sb + offBl + s * STG + lmB + nb * 16 * RB);
#pragma unroll
            for (int mr = 0; mr < 2; ++mr) {
                mma_bf16(acc[mr][nb * 2 + 0], ah[mr], bh[0], bh[2]);
                mma_bf16(acc[mr][nb * 2 + 1], ah[mr], bh[1], bh[3]);
                mma_bf16(acc[mr][nb * 2 + 0], ah[mr], bl[0], bl[2]);
                mma_bf16(acc[mr][nb * 2 + 1], ah[mr], bl[1], bl[3]);
                mma_bf16(acc[mr][nb * 2 + 0], al[mr], bh[0], bh[2]);
                mma_bf16(acc[mr][nb * 2 + 1], al[mr], bh[1], bh[3]);
            }
        }
        __syncthreads();
    }

    // ---- epilogue ----
#pragma unroll
    for (int mr = 0; mr < 2; ++mr) {
        const int r0 = m0 + wr * 32 + mr * 16 + (lane >> 2);
#pragma unroll
        for (int f = 0; f < 8; ++f) {
            const int col = n0 + wc * 64 + f * 8 + (lane & 3) * 2;
            if (col >= N) continue;
            const float b0 = bias[col], b1 = bias[col + 1];
#pragma unroll
            for (int h = 0; h < 2; ++h) {
                const int row = r0 + h * 8;
                if (row >= M) continue;
                float x0 = acc[mr][f][h * 2 + 0] + b0;
                float x1 = acc[mr][f][h * 2 + 1] + b1;
                if (MODE == 1) { x0 = gelu_exact(x0); x1 = gelu_exact(x1); }
                *reinterpret_cast<float2*>(C + (size_t)row * N + col) = make_float2(x0, x1);
            }
        }
    }
#undef ISSUE_B
#undef LOAD_A
#undef STORE_A
}

// ---------------- weight transpose + bf16 split (once per launch) -------------
__global__ __launch_bounds__(256)
void convert_weights(const float* __restrict__ Wv, const float* __restrict__ Wo,
                     const float* __restrict__ W1, const float* __restrict__ W2,
                     const float* __restrict__ Woff, const float* __restrict__ Wattn,
                     const float* __restrict__ boff, const float* __restrict__ battn) {
    const int b = blockIdx.x;
    const int k = threadIdx.x;
    if (b == 1168) {
        if (k < 96) g_boa[k] = boff[k];
        else if (k < 144) g_boa[k] = battn[k - 96];
        return;
    }
    const float* W; __nv_bfloat16* oh; __nv_bfloat16* ol; int n, nout, N;
    if (b < 256)       { W = Wv; oh = g_bv_h; ol = g_bv_l; n = b;        nout = n; N = 256; }
    else if (b < 512)  { W = Wo; oh = g_bo_h; ol = g_bo_l; n = b - 256;  nout = n; N = 256; }
    else if (b < 768)  { W = W1; oh = g_b1_h; ol = g_b1_l; n = b - 512;  nout = n; N = 256; }
    else if (b < 1024) { W = W2; oh = g_b2_h; ol = g_b2_l; n = b - 768;  nout = n; N = 256; }
    else {
        nout = b - 1024;  // 0..143
        oh = g_boa_h; ol = g_boa_l;
        if (nout < 96) { W = Woff;  n = nout;      N = 96; }
        else           { W = Wattn; n = nout - 96; N = 48; }
    }
    const float x = W[(size_t)k * N + n];
    const __nv_bfloat16 h = __float2bfloat16(x);
    const __nv_bfloat16 l = __float2bfloat16(x - __bfloat162float(h));
    oh[(size_t)nout * DDIM + k] = h;
    ol[(size_t)nout * DDIM + k] = l;
}

// ---------------- MSDA sampling: corner-parallel float4 gathers ---------------
__global__ __launch_bounds__(256)
void msda_sample_kernel(const float* __restrict__ oa, const float* __restrict__ v,
                        const float* __restrict__ ref, const int* __restrict__ ss,
                        float* __restrict__ out) {
    const int q = blockIdx.x;
    const int h = threadIdx.x >> 5;
    const int lane = threadIdx.x & 31;
    const int corner = lane >> 3;
    const int dx = corner & 1;
    const int dy = corner >> 1;
    const int cg = lane & 7;

    const int H = ss[0];
    const int W = ss[1];

    const float bx = __ldg(ref + q * 2 + 0) * (float)W - 0.5f;
    const float by = __ldg(ref + q * 2 + 1) * (float)H - 0.5f;

    const float* qa = oa + (size_t)q * 144;
    float lg[6];
    float mx = -1e30f;
#pragma unroll
    for (int p = 0; p < 6; ++p) {
        lg[p] = __ldg(qa + 96 + h * 6 + p);
        mx = fmaxf(mx, lg[p]);
    }
    float s = 0.f;
#pragma unroll
    for (int p = 0; p < 6; ++p) { lg[p] = __expf(lg[p] - mx); s += lg[p]; }
    const float inv = 1.f / s;

    const float4* vh = reinterpret_cast<const float4*>(v) + h * 8 + cg;
    float4 acc = make_float4(0.f, 0.f, 0.f, 0.f);

#pragma unroll
    for (int p = 0; p < 6; ++p) {
        const float ox = __ldg(qa + h * 12 + p * 2 + 0);
        const float oy = __ldg(qa + h * 12 + p * 2 + 1);
        const float lx = bx + ox;
        const float ly = by + oy;
        const float x0f = floorf(lx);
        const float y0f = floorf(ly);
        const float fx = lx - x0f;
        const float fy = ly - y0f;
        const int xi = (int)x0f + dx;
        const int yi = (int)y0f + dy;
        const float wx = dx ? fx : 1.f - fx;
        const float wy = dy ? fy : 1.f - fy;
        const bool valid = (xi >= 0) & (xi < W) & (yi >= 0) & (yi < H);
        const float w = valid ? (lg[p] * inv) * wx * wy : 0.f;
        const int xc = min(max(xi, 0), W - 1);
        const int yc = min(max(yi, 0), H - 1);
        const float4 val = __ldg(vh + (size_t)(yc * W + xc) * 64);
        acc.x += w * val.x;
        acc.y += w * val.y;
        acc.z += w * val.z;
        acc.w += w * val.w;
    }

#pragma unroll
    for (int o = 8; o <= 16; o <<= 1) {
        acc.x += __shfl_xor_sync(0xffffffffu, acc.x, o);
        acc.y += __shfl_xor_sync(0xffffffffu, acc.y, o);
        acc.z += __shfl_xor_sync(0xffffffffu, acc.z, o);
        acc.w += __shfl_xor_sync(0xffffffffu, acc.w, o);
    }
    if (lane < 8)
        *reinterpret_cast<float4*>(out + (size_t)q * DDIM + h * 32 + cg * 4) = acc;
}

// ---------------- fused residual + LayerNorm -----------------------------------
__global__ __launch_bounds__(256)
void ln_kernel(const float* __restrict__ x, const float* __restrict__ res,
               const float* __restrict__ g, const float* __restrict__ b,
               float* __restrict__ out) {
    const int row = blockIdx.x;
    const int tid = threadIdx.x;
    const float v = x[(size_t)row * DDIM + tid] + res[(size_t)row * DDIM + tid];

    float s = v, s2 = v * v;
#pragma unroll
    for (int o = 16; o; o >>= 1) {
        s  += __shfl_xor_sync(0xffffffffu, s, o);
        s2 += __shfl_xor_sync(0xffffffffu, s2, o);
    }
    __shared__ float sh[16];
    const int w = tid >> 5, lane = tid & 31;
    if (lane == 0) { sh[w] = s; sh[w + 8] = s2; }
    __syncthreads();
    if (tid == 0) {
        float a = 0.f, c = 0.f;
#pragma unroll
        for (int i = 0; i < 8; ++i) { a += sh[i]; c += sh[i + 8]; }
        sh[0] = a; sh[8] = c;
    }
    __syncthreads();
    const float mean = sh[0] * (1.f / 256.f);
    const float var  = sh[8] * (1.f / 256.f) - mean * mean;
    const float rstd = rsqrtf(var + 1e-5f);
    out[(size_t)row * DDIM + tid] = (v - mean) * rstd * g[tid] + b[tid];
}

// ---------------- launch --------------------------------------------------------
extern "C" void kernel_launch(void* const* d_in, const int* in_sizes, int n_in,
                              void* d_out, int out_size) {
    const float* query  = (const float*)d_in[0];
    const float* value  = (const float*)d_in[1];
    const float* refp   = (const float*)d_in[2];
    const int*   ss     = (const int*)d_in[3];
    const float* W_off  = (const float*)d_in[5];
    const float* b_off  = (const float*)d_in[6];
    const float* W_attn = (const float*)d_in[7];
    const float* b_attn = (const float*)d_in[8];
    const float* W_val  = (const float*)d_in[9];
    const float* b_val  = (const float*)d_in[10];
    const float* W_out  = (const float*)d_in[11];
    const float* b_out  = (const float*)d_in[12];
    const float* ln1_g  = (const float*)d_in[13];
    const float* ln1_b  = (const float*)d_in[14];
    const float* W1     = (const float*)d_in[15];
    const float* b1     = (const float*)d_in[16];
    const float* W2     = (const float*)d_in[17];
    const float* b2     = (const float*)d_in[18];
    const float* ln2_g  = (const float*)d_in[19];
    const float* ln2_b  = (const float*)d_in[20];
    float* out = (float*)d_out;

    const int M  = in_sizes[0] / DDIM;
    const int Mv = in_sizes[1] / DDIM;

    float *pv, *poa, *pmsda, *ptmp, *py, *pboa;
    __nv_bfloat16 *bvh, *bvl, *boh, *bol, *b1h, *b1l, *b2h, *b2l, *boah, *boal;
    cudaGetSymbolAddress((void**)&pv,    g_v);
    cudaGetSymbolAddress((void**)&poa,   g_oa);
    cudaGetSymbolAddress((void**)&pmsda, g_msda);
    cudaGetSymbolAddress((void**)&ptmp,  g_tmp);
    cudaGetSymbolAddress((void**)&py,    g_y);
    cudaGetSymbolAddress((void**)&pboa,  g_boa);
    cudaGetSymbolAddress((void**)&bvh,   g_bv_h);
    cudaGetSymbolAddress((void**)&bvl,   g_bv_l);
    cudaGetSymbolAddress((void**)&boh,   g_bo_h);
    cudaGetSymbolAddress((void**)&bol,   g_bo_l);
    cudaGetSymbolAddress((void**)&b1h,   g_b1_h);
    cudaGetSymbolAddress((void**)&b1l,   g_b1_l);
    cudaGetSymbolAddress((void**)&b2h,   g_b2_h);
    cudaGetSymbolAddress((void**)&b2l,   g_b2_l);
    cudaGetSymbolAddress((void**)&boah,  g_boa_h);
    cudaGetSymbolAddress((void**)&boal,  g_boa_l);

    const int SMEM = 8 * 128 * 48;  // 49152 bytes
    cudaFuncSetAttribute((gemm_mma<0, 1>), cudaFuncAttributeMaxDynamicSharedMemorySize, SMEM);
    cudaFuncSetAttribute((gemm_mma<1, 1>), cudaFuncAttributeMaxDynamicSharedMemorySize, SMEM);
    cudaFuncSetAttribute((gemm_mma<0, 0>), cudaFuncAttributeMaxDynamicSharedMemorySize, SMEM);

    const int gM  = (M + 127) / 128;
    const int gMv = (Mv + 127) / 128;

    // 0) weights -> transposed bf16 hi/lo
    convert_weights<<<1169, 256>>>(W_val, W_out, W1, W2, W_off, W_attn, b_off, b_attn);
    // 1) value projection
    gemm_mma<0, 1><<<dim3(2, gMv), 256, SMEM>>>(value, bvh, bvl, b_val, pv, Mv, DDIM);
    // 2) fused offsets+attn logits GEMM (N=144, nb-clamped)
    gemm_mma<0, 0><<<dim3(2, gM), 256, SMEM>>>(query, boah, boal, pboa, poa, M, 144);
    // 3) deformable sampling
    msda_sample_kernel<<<M, 256>>>(poa, pv, refp, ss, pmsda);
    // 4) output projection + residual + LN1
    gemm_mma<0, 1><<<dim3(2, gM), 256, SMEM>>>(pmsda, boh, bol, b_out, ptmp, M, DDIM);
    ln_kernel<<<M, 256>>>(ptmp, query, ln1_g, ln1_b, py);
    // 5) FFN
    gemm_mma<1, 1><<<dim3(2, gM), 256, SMEM>>>(py, b1h, b1l, b1, ptmp, M, DDIM);
    gemm_mma<0, 1><<<dim3(2, gM), 256, SMEM>>>(ptmp, b2h, b2l, b2, pmsda, M, DDIM);
    ln_kernel<<<M, 256>>>(pmsda, py, ln2_g, ln2_b, out);
}

// round 8
// speedup vs baseline: 1.3834x; 1.1407x over previous
#include <cuda_runtime.h>
#include <cuda_bf16.h>
#include <math.h>
#include <stdint.h>

#define DDIM 256
#define NQMAX 40000

// ---------------- scratch (device globals; zero-initialized, no allocation) --
__device__ __align__(16) float g_v   [NQMAX * DDIM];
__device__ __align__(16) float g_oa  [NQMAX * 144];
__device__ __align__(16) float g_msda[NQMAX * DDIM];
__device__ __align__(16) float g_tmp [NQMAX * DDIM];
__device__ __align__(16) float g_y   [NQMAX * DDIM];

// transposed + bf16-split weights: [N][K=256]   (oa padded to 256 rows, zeros)
__device__ __align__(16) __nv_bfloat16 g_bv_h[DDIM * DDIM];
__device__ __align__(16) __nv_bfloat16 g_bv_l[DDIM * DDIM];
__device__ __align__(16) __nv_bfloat16 g_bo_h[DDIM * DDIM];
__device__ __align__(16) __nv_bfloat16 g_bo_l[DDIM * DDIM];
__device__ __align__(16) __nv_bfloat16 g_b1_h[DDIM * DDIM];
__device__ __align__(16) __nv_bfloat16 g_b1_l[DDIM * DDIM];
__device__ __align__(16) __nv_bfloat16 g_b2_h[DDIM * DDIM];
__device__ __align__(16) __nv_bfloat16 g_b2_l[DDIM * DDIM];
__device__ __align__(16) __nv_bfloat16 g_boa_h[DDIM * DDIM];
__device__ __align__(16) __nv_bfloat16 g_boa_l[DDIM * DDIM];
__device__ __align__(16) float g_boa[144];

// ---------------- helpers ------------------------------------------------------
__device__ __forceinline__ uint32_t smem_u32(const void* p) {
    uint32_t a;
    asm("{ .reg .u64 t; cvta.to.shared.u64 t, %1; cvt.u32.u64 %0, t; }" : "=r"(a) : "l"(p));
    return a;
}

__device__ __forceinline__ uint32_t pack_bf16(__nv_bfloat16 x, __nv_bfloat16 y) {
    __nv_bfloat162 t(x, y);
    return *reinterpret_cast<uint32_t*>(&t);
}

__device__ __forceinline__ float gelu_exact(float x) {
    return 0.5f * x * (1.0f + erff(x * 0.70710678118654752f));
}

#define LDSM4(r, addr) \
    asm volatile("ldmatrix.sync.aligned.m8n8.x4.shared.b16 {%0,%1,%2,%3}, [%4];" \
        : "=r"((r)[0]), "=r"((r)[1]), "=r"((r)[2]), "=r"((r)[3]) : "r"(addr))

#define CP_ASYNC16(dst, src) \
    asm volatile("cp.async.ca.shared.global [%0], [%1], 16;" :: "r"(dst), "l"(src))
#define CP_COMMIT() asm volatile("cp.async.commit_group;" ::: "memory")
#define CP_WAIT(n)  asm volatile("cp.async.wait_group %0;" :: "n"(n) : "memory")

__device__ __forceinline__ void mma_bf16(float* d, const uint32_t* a,
                                         uint32_t b0, uint32_t b1) {
    asm volatile(
        "mma.sync.aligned.m16n8k16.row.col.f32.bf16.bf16.f32 "
        "{%0,%1,%2,%3}, {%4,%5,%6,%7}, {%8,%9}, {%0,%1,%2,%3};"
        : "+f"(d[0]), "+f"(d[1]), "+f"(d[2]), "+f"(d[3])
        : "r"(a[0]), "r"(a[1]), "r"(a[2]), "r"(a[3]), "r"(b0), "r"(b1));
}

// ---------------- HMMA GEMM (R4 baseline; static-unroll nb clamp) --------------
// C = A[M][256] @ B^T + bias.  CTA tile 128x128, 8 warps (4x2), BK=16.
// MODE 0: +bias; MODE 1: +bias then exact GELU.
// FULLN=1: all warp columns valid. FULLN=0: clamp via unrolled break (no spills).
template<int MODE, int FULLN>
__global__ __launch_bounds__(256, 2)
void gemm_mma(const float* __restrict__ A,
              const __nv_bfloat16* __restrict__ Bh,
              const __nv_bfloat16* __restrict__ Bl,
              const float* __restrict__ bias,
              float* __restrict__ C, int M, int N) {
    extern __shared__ __align__(128) char smem[];
    const uint32_t sb = smem_u32(smem);
    const int tid = threadIdx.x;
    const int wid = tid >> 5;
    const int lane = tid & 31;
    const int m0 = blockIdx.y * 128;
    const int n0 = blockIdx.x * 128;
    const int wr = wid & 3;
    const int wc = wid >> 2;

    constexpr int RB = 48;         // smem row bytes (32 data + 16 pad)
    constexpr int STG = 128 * RB;  // 6144 bytes per buffer
    const uint32_t offAh = 0, offAl = 2 * STG, offBh = 4 * STG, offBl = 6 * STG;

    // valid nb count for this warp (16-col groups inside its 64-col slab)
    int nbLim = 4;
    if (!FULLN) {
        const int rem = N - n0 - wc * 64;
        nbLim = rem >= 64 ? 4 : (rem <= 0 ? 0 : (rem + 15) >> 4);
    }

    float acc[2][8][4];
#pragma unroll
    for (int i = 0; i < 2; ++i)
#pragma unroll
        for (int j = 0; j < 8; ++j)
#pragma unroll
            for (int k = 0; k < 4; ++k) acc[i][j][k] = 0.f;

    float4 pa[2];
    const int brow = tid >> 1;
    const int bcol = (tid & 1) * 16;
    const __nv_bfloat16* bSrcH = Bh + (size_t)(n0 + brow) * DDIM + (tid & 1) * 8;
    const __nv_bfloat16* bSrcL = Bl + (size_t)(n0 + brow) * DDIM + (tid & 1) * 8;
    const uint32_t bDstOff = brow * RB + bcol;

#define ISSUE_B(c, s) do { \
    CP_ASYNC16(sb + offBh + (s) * STG + bDstOff, bSrcH + (c) * 16); \
    CP_ASYNC16(sb + offBl + (s) * STG + bDstOff, bSrcL + (c) * 16); \
    CP_COMMIT(); } while (0)

#define LOAD_A(c) do { \
    _Pragma("unroll") \
    for (int i = 0; i < 2; ++i) { \
        const int slot = tid + i * 256; \
        const int r = slot >> 2, qq = slot & 3; \
        if (m0 + r < M) \
            pa[i] = *reinterpret_cast<const float4*>(A + (size_t)(m0 + r) * DDIM + (c) * 16 + qq * 4); \
        else pa[i] = make_float4(0.f, 0.f, 0.f, 0.f); \
    } } while (0)

#define STORE_A(s) do { \
    _Pragma("unroll") \
    for (int i = 0; i < 2; ++i) { \
        const int slot = tid + i * 256; \
        const int r = slot >> 2, qq = slot & 3; \
        __nv_bfloat16 h0 = __float2bfloat16(pa[i].x); \
        __nv_bfloat16 h1 = __float2bfloat16(pa[i].y); \
        __nv_bfloat16 h2 = __float2bfloat16(pa[i].z); \
        __nv_bfloat16 h3 = __float2bfloat16(pa[i].w); \
        uint2 hv = make_uint2(pack_bf16(h0, h1), pack_bf16(h2, h3)); \
        uint2 lv = make_uint2( \
            pack_bf16(__float2bfloat16(pa[i].x - __bfloat162float(h0)), \
                      __float2bfloat16(pa[i].y - __bfloat162float(h1))), \
            pack_bf16(__float2bfloat16(pa[i].z - __bfloat162float(h2)), \
                      __float2bfloat16(pa[i].w - __bfloat162float(h3)))); \
        *reinterpret_cast<uint2*>(smem + offAh + (s) * STG + r * RB + qq * 8) = hv; \
        *reinterpret_cast<uint2*>(smem + offAl + (s) * STG + r * RB + qq * 8) = lv; \
    } } while (0)

    ISSUE_B(0, 0);
    LOAD_A(0);

    const uint32_t lmA = (wr * 32 + (lane & 15)) * RB + (lane >> 4) * 16;
    const uint32_t lmB = (wc * 64 + (lane & 15)) * RB + (lane >> 4) * 16;

    for (int c = 0; c < 16; ++c) {
        const int s = c & 1;
        STORE_A(s);
        if (c < 15) { ISSUE_B(c + 1, s ^ 1); CP_WAIT(1); }
        else        { CP_WAIT(0); }
        __syncthreads();
        if (c < 15) LOAD_A(c + 1);

        uint32_t ah[2][4], al[2][4];
#pragma unroll
        for (int mr = 0; mr < 2; ++mr) {
            LDSM4(ah[mr], sb + offAh + s * STG + lmA + mr * 16 * RB);
            LDSM4(al[mr], sb + offAl + s * STG + lmA + mr * 16 * RB);
        }
#pragma unroll
        for (int nb = 0; nb < 4; ++nb) {          // constant trip count: static acc idx
            if (!FULLN && nb >= nbLim) break;     // predicated tail, no dynamic indexing
            uint32_t bh[4], bl[4];
            LDSM4(bh, sb + offBh + s * STG + lmB + nb * 16 * RB);
            LDSM4(bl, sb + offBl + s * STG + lmB + nb * 16 * RB);
#pragma unroll
            for (int mr = 0; mr < 2; ++mr) {
                mma_bf16(acc[mr][nb * 2 + 0], ah[mr], bh[0], bh[2]);
                mma_bf16(acc[mr][nb * 2 + 1], ah[mr], bh[1], bh[3]);
                mma_bf16(acc[mr][nb * 2 + 0], ah[mr], bl[0], bl[2]);
                mma_bf16(acc[mr][nb * 2 + 1], ah[mr], bl[1], bl[3]);
                mma_bf16(acc[mr][nb * 2 + 0], al[mr], bh[0], bh[2]);
                mma_bf16(acc[mr][nb * 2 + 1], al[mr], bh[1], bh[3]);
            }
        }
        __syncthreads();
    }

    // ---- epilogue ----
#pragma unroll
    for (int mr = 0; mr < 2; ++mr) {
        const int r0 = m0 + wr * 32 + mr * 16 + (lane >> 2);
#pragma unroll
        for (int f = 0; f < 8; ++f) {
            const int col = n0 + wc * 64 + f * 8 + (lane & 3) * 2;
            if (col >= N) continue;
            const float b0 = bias[col], b1 = bias[col + 1];
#pragma unroll
            for (int h = 0; h < 2; ++h) {
                const int row = r0 + h * 8;
                if (row >= M) continue;
                float x0 = acc[mr][f][h * 2 + 0] + b0;
                float x1 = acc[mr][f][h * 2 + 1] + b1;
                if (MODE == 1) { x0 = gelu_exact(x0); x1 = gelu_exact(x1); }
                *reinterpret_cast<float2*>(C + (size_t)row * N + col) = make_float2(x0, x1);
            }
        }
    }
#undef ISSUE_B
#undef LOAD_A
#undef STORE_A
}

// ---------------- weight transpose + bf16 split (once per launch) -------------
__global__ __launch_bounds__(256)
void convert_weights(const float* __restrict__ Wv, const float* __restrict__ Wo,
                     const float* __restrict__ W1, const float* __restrict__ W2,
                     const float* __restrict__ Woff, const float* __restrict__ Wattn,
                     const float* __restrict__ boff, const float* __restrict__ battn) {
    const int b = blockIdx.x;
    const int k = threadIdx.x;
    if (b == 1168) {
        if (k < 96) g_boa[k] = boff[k];
        else if (k < 144) g_boa[k] = battn[k - 96];
        return;
    }
    const float* W; __nv_bfloat16* oh; __nv_bfloat16* ol; int n, nout, N;
    if (b < 256)       { W = Wv; oh = g_bv_h; ol = g_bv_l; n = b;        nout = n; N = 256; }
    else if (b < 512)  { W = Wo; oh = g_bo_h; ol = g_bo_l; n = b - 256;  nout = n; N = 256; }
    else if (b < 768)  { W = W1; oh = g_b1_h; ol = g_b1_l; n = b - 512;  nout = n; N = 256; }
    else if (b < 1024) { W = W2; oh = g_b2_h; ol = g_b2_l; n = b - 768;  nout = n; N = 256; }
    else {
        nout = b - 1024;  // 0..143
        oh = g_boa_h; ol = g_boa_l;
        if (nout < 96) { W = Woff;  n = nout;      N = 96; }
        else           { W = Wattn; n = nout - 96; N = 48; }
    }
    const float x = W[(size_t)k * N + n];
    const __nv_bfloat16 h = __float2bfloat16(x);
    const __nv_bfloat16 l = __float2bfloat16(x - __bfloat162float(h));
    oh[(size_t)nout * DDIM + k] = h;
    ol[(size_t)nout * DDIM + k] = l;
}

// ---------------- MSDA sampling: corner-parallel float4 gathers ---------------
__global__ __launch_bounds__(256)
void msda_sample_kernel(const float* __restrict__ oa, const float* __restrict__ v,
                        const float* __restrict__ ref, const int* __restrict__ ss,
                        float* __restrict__ out) {
    const int q = blockIdx.x;
    const int h = threadIdx.x >> 5;
    const int lane = threadIdx.x & 31;
    const int corner = lane >> 3;
    const int dx = corner & 1;
    const int dy = corner >> 1;
    const int cg = lane & 7;

    const int H = ss[0];
    const int W = ss[1];

    const float bx = __ldg(ref + q * 2 + 0) * (float)W - 0.5f;
    const float by = __ldg(ref + q * 2 + 1) * (float)H - 0.5f;

    const float* qa = oa + (size_t)q * 144;
    float lg[6];
    float mx = -1e30f;
#pragma unroll
    for (int p = 0; p < 6; ++p) {
        lg[p] = __ldg(qa + 96 + h * 6 + p);
        mx = fmaxf(mx, lg[p]);
    }
    float s = 0.f;
#pragma unroll
    for (int p = 0; p < 6; ++p) { lg[p] = __expf(lg[p] - mx); s += lg[p]; }
    const float inv = 1.f / s;

    const float4* vh = reinterpret_cast<const float4*>(v) + (h * 8 + cg);
    float4 acc = make_float4(0.f, 0.f, 0.f, 0.f);

#pragma unroll
    for (int p = 0; p < 6; ++p) {
        const float ox = __ldg(qa + h * 12 + p * 2 + 0);
        const float oy = __ldg(qa + h * 12 + p * 2 + 1);
        const float lx = bx + ox;
        const float ly = by + oy;
        const float x0f = floorf(lx);
        const float y0f = floorf(ly);
        const float fx = lx - x0f;
        const float fy = ly - y0f;
        const int xi = (int)x0f + dx;
        const int yi = (int)y0f + dy;
        const float wx = dx ? fx : 1.f - fx;
        const float wy = dy ? fy : 1.f - fy;
        const bool valid = (xi >= 0) & (xi < W) & (yi >= 0) & (yi < H);
        const float w = valid ? (lg[p] * inv) * wx * wy : 0.f;
        const uint32_t xc = (uint32_t)min(max(xi, 0), W - 1);
        const uint32_t yc = (uint32_t)min(max(yi, 0), H - 1);
        const uint32_t off = (yc * (uint32_t)W + xc) * 64u;   // 32-bit index math
        const float4 val = __ldg(vh + off);
        acc.x += w * val.x;
        acc.y += w * val.y;
        acc.z += w * val.z;
        acc.w += w * val.w;
    }

#pragma unroll
    for (int o = 8; o <= 16; o <<= 1) {
        acc.x += __shfl_xor_sync(0xffffffffu, acc.x, o);
        acc.y += __shfl_xor_sync(0xffffffffu, acc.y, o);
        acc.z += __shfl_xor_sync(0xffffffffu, acc.z, o);
        acc.w += __shfl_xor_sync(0xffffffffu, acc.w, o);
    }
    if (lane < 8)
        *reinterpret_cast<float4*>(out + (size_t)q * DDIM + h * 32 + cg * 4) = acc;
}

// ---------------- fused residual + LayerNorm -----------------------------------
__global__ __launch_bounds__(256)
void ln_kernel(const float* __restrict__ x, const float* __restrict__ res,
               const float* __restrict__ g, const float* __restrict__ b,
               float* __restrict__ out) {
    const int row = blockIdx.x;
    const int tid = threadIdx.x;
    const float v = x[(size_t)row * DDIM + tid] + res[(size_t)row * DDIM + tid];

    float s = v, s2 = v * v;
#pragma unroll
    for (int o = 16; o; o >>= 1) {
        s  += __shfl_xor_sync(0xffffffffu, s, o);
        s2 += __shfl_xor_sync(0xffffffffu, s2, o);
    }
    __shared__ float sh[16];
    const int w = tid >> 5, lane = tid & 31;
    if (lane == 0) { sh[w] = s; sh[w + 8] = s2; }
    __syncthreads();
    if (tid == 0) {
        float a = 0.f, c = 0.f;
#pragma unroll
        for (int i = 0; i < 8; ++i) { a += sh[i]; c += sh[i + 8]; }
        sh[0] = a; sh[8] = c;
    }
    __syncthreads();
    const float mean = sh[0] * (1.f / 256.f);
    const float var  = sh[8] * (1.f / 256.f) - mean * mean;
    const float rstd = rsqrtf(var + 1e-5f);
    out[(size_t)row * DDIM + tid] = (v - mean) * rstd * g[tid] + b[tid];
}

// ---------------- launch --------------------------------------------------------
extern "C" void kernel_launch(void* const* d_in, const int* in_sizes, int n_in,
                              void* d_out, int out_size) {
    const float* query  = (const float*)d_in[0];
    const float* value  = (const float*)d_in[1];
    const float* refp   = (const float*)d_in[2];
    const int*   ss     = (const int*)d_in[3];
    const float* W_off  = (const float*)d_in[5];
    const float* b_off  = (const float*)d_in[6];
    const float* W_attn = (const float*)d_in[7];
    const float* b_attn = (const float*)d_in[8];
    const float* W_val  = (const float*)d_in[9];
    const float* b_val  = (const float*)d_in[10];
    const float* W_out  = (const float*)d_in[11];
    const float* b_out  = (const float*)d_in[12];
    const float* ln1_g  = (const float*)d_in[13];
    const float* ln1_b  = (const float*)d_in[14];
    const float* W1     = (const float*)d_in[15];
    const float* b1     = (const float*)d_in[16];
    const float* W2     = (const float*)d_in[17];
    const float* b2     = (const float*)d_in[18];
    const float* ln2_g  = (const float*)d_in[19];
    const float* ln2_b  = (const float*)d_in[20];
    float* out = (float*)d_out;

    const int M  = in_sizes[0] / DDIM;
    const int Mv = in_sizes[1] / DDIM;

    float *pv, *poa, *pmsda, *ptmp, *py, *pboa;
    __nv_bfloat16 *bvh, *bvl, *boh, *bol, *b1h, *b1l, *b2h, *b2l, *boah, *boal;
    cudaGetSymbolAddress((void**)&pv,    g_v);
    cudaGetSymbolAddress((void**)&poa,   g_oa);
    cudaGetSymbolAddress((void**)&pmsda, g_msda);
    cudaGetSymbolAddress((void**)&ptmp,  g_tmp);
    cudaGetSymbolAddress((void**)&py,    g_y);
    cudaGetSymbolAddress((void**)&pboa,  g_boa);
    cudaGetSymbolAddress((void**)&bvh,   g_bv_h);
    cudaGetSymbolAddress((void**)&bvl,   g_bv_l);
    cudaGetSymbolAddress((void**)&boh,   g_bo_h);
    cudaGetSymbolAddress((void**)&bol,   g_bo_l);
    cudaGetSymbolAddress((void**)&b1h,   g_b1_h);
    cudaGetSymbolAddress((void**)&b1l,   g_b1_l);
    cudaGetSymbolAddress((void**)&b2h,   g_b2_h);
    cudaGetSymbolAddress((void**)&b2l,   g_b2_l);
    cudaGetSymbolAddress((void**)&boah,  g_boa_h);
    cudaGetSymbolAddress((void**)&boal,  g_boa_l);

    const int SMEM = 8 * 128 * 48;  // 49152 bytes
    cudaFuncSetAttribute((gemm_mma<0, 1>), cudaFuncAttributeMaxDynamicSharedMemorySize, SMEM);
    cudaFuncSetAttribute((gemm_mma<1, 1>), cudaFuncAttributeMaxDynamicSharedMemorySize, SMEM);
    cudaFuncSetAttribute((gemm_mma<0, 0>), cudaFuncAttributeMaxDynamicSharedMemorySize, SMEM);

    const int gM  = (M + 127) / 128;
    const int gMv = (Mv + 127) / 128;

    // 0) weights -> transposed bf16 hi/lo
    convert_weights<<<1169, 256>>>(W_val, W_out, W1, W2, W_off, W_attn, b_off, b_attn);
    // 1) value projection
    gemm_mma<0, 1><<<dim3(2, gMv), 256, SMEM>>>(value, bvh, bvl, b_val, pv, Mv, DDIM);
    // 2) fused offsets+attn logits GEMM (N=144, statically clamped)
    gemm_mma<0, 0><<<dim3(2, gM), 256, SMEM>>>(query, boah, boal, pboa, poa, M, 144);
    // 3) deformable sampling
    msda_sample_kernel<<<M, 256>>>(poa, pv, refp, ss, pmsda);
    // 4) output projection + residual + LN1
    gemm_mma<0, 1><<<dim3(2, gM), 256, SMEM>>>(pmsda, boh, bol, b_out, ptmp, M, DDIM);
    ln_kernel<<<M, 256>>>(ptmp, query, ln1_g, ln1_b, py);
    // 5) FFN
    gemm_mma<1, 1><<<dim3(2, gM), 256, SMEM>>>(py, b1h, b1l, b1, ptmp, M, DDIM);
    gemm_mma<0, 1><<<dim3(2, gM), 256, SMEM>>>(ptmp, b2h, b2l, b2, pmsda, M, DDIM);
    ln_kernel<<<M, 256>>>(pmsda, py, ln2_g, ln2_b, out);
}